// round 11
// baseline (speedup 1.0000x reference)
#include <cuda_runtime.h>
#include <cuda_bf16.h>

#define BB 64
#define VV 64
#define TT 256
#define FF 64
#define NT  256
#define BPB 8     // one warp per batch row, per tile
#define AP  68    // adj row pitch: 272B, 16B-aligned; LDS.128 conflict-free (68 mod 32 = 4)

// fast sigmoid: 1 MUFU (EX2 via __expf) + bit-trick reciprocal + 2 Newton steps
__device__ __forceinline__ float fsig(float a) {
    float e = __expf(-a);                 // EX2 + mul
    float d = 1.0f + e;                   // d in (1, +inf), normal positive
    float y = __uint_as_float(0x7EF311C3u - __float_as_uint(d));
    y = y * (2.0f - d * y);
    y = y * (2.0f - d * y);               // rel err ~1e-6
    return y;
}

// ---------------------------------------------------------------------------
// Depth-2 pipelined fused kernel. Block = (bp, t): ONE timestep, TWO batch
// tiles (b1 = 8*bp and b2 = b1+32) sharing one adj. Grid (4,256)=1024 blocks
// = ONE wave at 8 CTAs/SM.
//   stage adj (sigmoid once for both tiles) + xs tile1; ONE __syncthreads.
//   per warp: dot1 -> prefetch tile2 X row to regs -> stream tile1 row (16KB)
//             -> STS tile2 row -> dot2 -> stream tile2 row.
// Tile2 phase-1 (gather latency, wavefronts, dot issue) hides under tile1
// stores; no block barrier after the first.
// ---------------------------------------------------------------------------
__global__ __launch_bounds__(NT, 8)
void gnn_fused(const float* __restrict__ X,
               const float* __restrict__ A,
               const float* __restrict__ W,
               float* __restrict__ out)
{
    __shared__ float adj[VV][AP];       // 17.4 KB
    __shared__ float xs[BPB][VV];       // 2 KB  (reused by tile2, warp-private rows)
    __shared__ float hs[BPB][VV];       // 2 KB  (reused by tile2, warp-private rows)

    const int bp  = blockIdx.x;         // 0..3   (fast dim: same-t blocks adjacent)
    const int t   = blockIdx.y;         // 0..255
    const int tid = threadIdx.x;
    const int wid = tid >> 5;           // 0..7
    const int lid = tid & 31;
    const int b1  = bp * BPB;           // tile1 batches
    const int b2  = b1 + 32;            // tile2 batches

    // ---- adj = sigmoid(A_t) off-diag, 1 on diag; shared by BOTH tiles ----
    const float4* Ag = reinterpret_cast<const float4*>(A + (size_t)t * VV * VV);
    #pragma unroll 2
    for (int k = 0; k < 4; ++k) {
        int i  = tid + k * NT;          // float4 index 0..1023, coalesced (L2-hot x4)
        int v  = i >> 4;
        int w4 = i & 15;
        float4 a = Ag[i];
        float4 s;
        s.x = fsig(a.x); s.y = fsig(a.y); s.z = fsig(a.z); s.w = fsig(a.w);
        int wbase = w4 * 4;
        if (v == wbase + 0) s.x = 1.0f;
        if (v == wbase + 1) s.y = 1.0f;
        if (v == wbase + 2) s.z = 1.0f;
        if (v == wbase + 3) s.w = 1.0f;
        *reinterpret_cast<float4*>(&adj[v][wbase]) = s;
    }

    // ---- stage xs tile1: xs[bl][w] = X[b1+bl, w, t] ----
    #pragma unroll 2
    for (int k = 0; k < (BPB * VV) / NT; ++k) {      // 2 iters
        int i  = tid + k * NT;
        int bl = i >> 6, w = i & 63;
        xs[bl][w] = X[((size_t)(b1 + bl) * VV + w) * TT + t];
    }

    const float4 wv = reinterpret_cast<const float4*>(W)[lid & 15];

    __syncthreads();                    // ONLY block-wide barrier

    // ================= tile 1 =================
    {
        float s0 = 0.f, s1 = 0.f;
        #pragma unroll
        for (int w4 = 0; w4 < 16; ++w4) {
            float4 p = *reinterpret_cast<const float4*>(&adj[lid     ][w4 * 4]);
            float4 q = *reinterpret_cast<const float4*>(&adj[lid + 32][w4 * 4]);
            float4 x = *reinterpret_cast<const float4*>(&xs[wid][w4 * 4]);
            s0 = fmaf(p.x, x.x, s0); s0 = fmaf(p.y, x.y, s0);
            s0 = fmaf(p.z, x.z, s0); s0 = fmaf(p.w, x.w, s0);
            s1 = fmaf(q.x, x.x, s1); s1 = fmaf(q.y, x.y, s1);
            s1 = fmaf(q.z, x.z, s1); s1 = fmaf(q.w, x.w, s1);
        }
        hs[wid][lid]      = s0;
        hs[wid][lid + 32] = s1;
    }
    __syncwarp();

    // prefetch tile2 X row (warp-private): latency hides under tile1 stores
    const float* xrow2 = X + (size_t)(b2 + wid) * VV * TT + t;
    float rx0 = xrow2[(size_t)lid * TT];
    float rx1 = xrow2[(size_t)(lid + 32) * TT];

    // stream tile1 row: 16 KB, coalesced float4, evict-first
    {
        float4* o = reinterpret_cast<float4*>(
            out + ((size_t)(b1 + wid) * TT + t) * (VV * FF));
        #pragma unroll 4
        for (int j = 0; j < (VV * FF / 4) / 32; ++j) {   // 32 iters
            int p = j * 32 + lid;
            float h = hs[wid][p >> 4];
            float4 r;
            r.x = h * wv.x; r.y = h * wv.y; r.z = h * wv.z; r.w = h * wv.w;
            r.x = fmaxf(r.x, 0.01f * r.x);
            r.y = fmaxf(r.y, 0.01f * r.y);
            r.z = fmaxf(r.z, 0.01f * r.z);
            r.w = fmaxf(r.w, 0.01f * r.w);
            __stcs(&o[p], r);
        }
    }

    // ================= tile 2 (no block barrier: warp-private rows) =========
    xs[wid][lid]      = rx0;
    xs[wid][lid + 32] = rx1;
    __syncwarp();

    {
        float s0 = 0.f, s1 = 0.f;
        #pragma unroll
        for (int w4 = 0; w4 < 16; ++w4) {
            float4 p = *reinterpret_cast<const float4*>(&adj[lid     ][w4 * 4]);
            float4 q = *reinterpret_cast<const float4*>(&adj[lid + 32][w4 * 4]);
            float4 x = *reinterpret_cast<const float4*>(&xs[wid][w4 * 4]);
            s0 = fmaf(p.x, x.x, s0); s0 = fmaf(p.y, x.y, s0);
            s0 = fmaf(p.z, x.z, s0); s0 = fmaf(p.w, x.w, s0);
            s1 = fmaf(q.x, x.x, s1); s1 = fmaf(q.y, x.y, s1);
            s1 = fmaf(q.z, x.z, s1); s1 = fmaf(q.w, x.w, s1);
        }
        hs[wid][lid]      = s0;
        hs[wid][lid + 32] = s1;
    }
    __syncwarp();

    {
        float4* o = reinterpret_cast<float4*>(
            out + ((size_t)(b2 + wid) * TT + t) * (VV * FF));
        #pragma unroll 4
        for (int j = 0; j < (VV * FF / 4) / 32; ++j) {   // 32 iters
            int p = j * 32 + lid;
            float h = hs[wid][p >> 4];
            float4 r;
            r.x = h * wv.x; r.y = h * wv.y; r.z = h * wv.z; r.w = h * wv.w;
            r.x = fmaxf(r.x, 0.01f * r.x);
            r.y = fmaxf(r.y, 0.01f * r.y);
            r.z = fmaxf(r.z, 0.01f * r.z);
            r.w = fmaxf(r.w, 0.01f * r.w);
            __stcs(&o[p], r);
        }
    }
}

extern "C" void kernel_launch(void* const* d_in, const int* in_sizes, int n_in,
                              void* d_out, int out_size) {
    const float* X = (const float*)d_in[0];   // [64, 64, 256]
    const float* A = (const float*)d_in[1];   // [256, 64, 64]
    const float* W = (const float*)d_in[2];   // [64, 1]
    float* out = (float*)d_out;               // [64, 256, 4096]
    (void)in_sizes; (void)n_in; (void)out_size;

    dim3 grid(4, TT);                         // (4, 256) = 1024 blocks, ~1 wave
    gnn_fused<<<grid, NT>>>(X, A, W, out);
}